// round 3
// baseline (speedup 1.0000x reference)
#include <cuda_runtime.h>
#include <math.h>

#define NN 8192
#define TT 60
#define DD 6
#define HH 64
#define GG 192
#define RPC 56
#define GRU_NTH 448
#define HB (HH*RPC)

__device__ float g_xt[TT*DD*NN];
__device__ float g_hidden[NN*HH];
__device__ float g_s1[NN];
__device__ float g_s2[NN];
__device__ unsigned long long g_keys[NN];
__device__ float g_s1s[NN];
__device__ int   g_perm[NN];
__device__ double g_prefP[(NN+1)*HH];
__device__ double g_prefQ[(NN+1)*HH];
__device__ double g_prefE[(NN+1)*2];

__device__ __forceinline__ float sig_f(float x){ return 1.f/(1.f+__expf(-x)); }
__device__ __forceinline__ float tanh_f(float x){ return 1.f-2.f/(__expf(2.f*x)+1.f); }

__global__ void transpose_kernel(const float* __restrict__ x){
    int idx = blockIdx.x*256 + threadIdx.x;
    if (idx >= TT*DD*NN) return;
    int t = idx/(DD*NN);
    int r = idx - t*(DD*NN);
    int d = r >> 13;
    int n = r & (NN-1);
    g_xt[idx] = x[n*(DD*TT) + d*TT + t];
}

__global__ __launch_bounds__(GRU_NTH,1) void gru_kernel(
    const float* __restrict__ Wih0, const float* __restrict__ Whh0,
    const float* __restrict__ bih0, const float* __restrict__ bhh0,
    const float* __restrict__ Wih1, const float* __restrict__ Whh1,
    const float* __restrict__ bih1, const float* __restrict__ bhh1)
{
    extern __shared__ float sm[];
    float* sWhh0 = sm;
    float* sWih1 = sm + 12288;
    float* sWhh1 = sm + 24576;
    float* sWih0 = sm + 36864;
    float* sB    = sm + 38016;
    float* sH0   = sm + 38784;
    float* sH1   = sm + 45952;
    const int tid = threadIdx.x;

    for (int idx = tid; idx < GG*HH; idx += GRU_NTH){
        int o = idx >> 6, k = idx & 63;
        sWhh0[k*GG+o] = Whh0[idx];
        sWih1[k*GG+o] = Wih1[idx];
        sWhh1[k*GG+o] = Whh1[idx];
    }
    for (int idx = tid; idx < GG*DD; idx += GRU_NTH){
        int o = idx/DD, d = idx - o*DD;
        sWih0[d*GG+o] = Wih0[idx];
    }
    for (int idx = tid; idx < GG; idx += GRU_NTH){
        sB[idx]     = bih0[idx];
        sB[192+idx] = bhh0[idx];
        sB[384+idx] = bih1[idx];
        sB[576+idx] = bhh1[idx];
    }
    for (int idx = tid; idx < 2*HB; idx += GRU_NTH){ sH0[idx]=0.f; sH1[idx]=0.f; }
    __syncthreads();

    const int j  = tid & 63;
    const int r0 = (tid >> 6) << 3;
    const int nbase = blockIdx.x*RPC + r0;
    const bool v8 = (nbase + 7) < NN;

    const float b0r = sB[j]      + sB[192+j];
    const float b0z = sB[64+j]   + sB[256+j];
    const float b0i = sB[128+j];
    const float b0h = sB[320+j];
    const float b1r = sB[384+j]  + sB[576+j];
    const float b1z = sB[448+j]  + sB[640+j];
    const float b1i = sB[512+j];
    const float b1h = sB[704+j];

    #pragma unroll 1
    for (int t = 0; t < TT; t++){
        const int p = t & 1;
        const float* h0r = sH0 + p*HB;
        float*       h0w = sH0 + (p^1)*HB;
        float ar[8], az[8], ai[8], ah[8];
        #pragma unroll
        for (int rr=0; rr<8; rr++){ ar[rr]=b0r; az[rr]=b0z; ai[rr]=b0i; ah[rr]=b0h; }

        #pragma unroll
        for (int d=0; d<DD; d++){
            float xv[8];
            const float* xp = g_xt + (t*DD+d)*NN + nbase;
            if (v8){
                float4 a = *(const float4*)xp;
                float4 b = *(const float4*)(xp+4);
                xv[0]=a.x; xv[1]=a.y; xv[2]=a.z; xv[3]=a.w;
                xv[4]=b.x; xv[5]=b.y; xv[6]=b.z; xv[7]=b.w;
            } else {
                #pragma unroll
                for (int rr=0; rr<8; rr++) xv[rr] = (nbase+rr < NN) ? xp[rr] : 0.f;
            }
            float wr = sWih0[d*GG+j], wz = sWih0[d*GG+64+j], wn = sWih0[d*GG+128+j];
            #pragma unroll
            for (int rr=0; rr<8; rr++){
                ar[rr] += wr*xv[rr]; az[rr] += wz*xv[rr]; ai[rr] += wn*xv[rr];
            }
        }
        #pragma unroll 8
        for (int k=0; k<HH; k++){
            float wr = sWhh0[k*GG+j], wz = sWhh0[k*GG+64+j], wn = sWhh0[k*GG+128+j];
            float4 ha = *(const float4*)(h0r + k*RPC + r0);
            float4 hb = *(const float4*)(h0r + k*RPC + r0 + 4);
            float hv[8] = {ha.x,ha.y,ha.z,ha.w,hb.x,hb.y,hb.z,hb.w};
            #pragma unroll
            for (int rr=0; rr<8; rr++){
                ar[rr] += wr*hv[rr]; az[rr] += wz*hv[rr]; ah[rr] += wn*hv[rr];
            }
        }
        #pragma unroll
        for (int rr=0; rr<8; rr++){
            float r = sig_f(ar[rr]);
            float z = sig_f(az[rr]);
            float nv = tanh_f(ai[rr] + r*ah[rr]);
            float hold = h0r[j*RPC + r0 + rr];
            h0w[j*RPC + r0 + rr] = nv + z*(hold - nv);
        }
        __syncthreads();

        const float* h1r = sH1 + p*HB;
        float*       h1w = sH1 + (p^1)*HB;
        #pragma unroll
        for (int rr=0; rr<8; rr++){ ar[rr]=b1r; az[rr]=b1z; ai[rr]=b1i; ah[rr]=b1h; }
        #pragma unroll 4
        for (int k=0; k<HH; k++){
            float uir = sWih1[k*GG+j], uiz = sWih1[k*GG+64+j], uin = sWih1[k*GG+128+j];
            float vhr = sWhh1[k*GG+j], vhz = sWhh1[k*GG+64+j], vhn = sWhh1[k*GG+128+j];
            float4 ya = *(const float4*)(h0w + k*RPC + r0);
            float4 yb = *(const float4*)(h0w + k*RPC + r0 + 4);
            float4 ga = *(const float4*)(h1r + k*RPC + r0);
            float4 gb = *(const float4*)(h1r + k*RPC + r0 + 4);
            float yv[8] = {ya.x,ya.y,ya.z,ya.w,yb.x,yb.y,yb.z,yb.w};
            float gv[8] = {ga.x,ga.y,ga.z,ga.w,gb.x,gb.y,gb.z,gb.w};
            #pragma unroll
            for (int rr=0; rr<8; rr++){
                ar[rr] += uir*yv[rr]; az[rr] += uiz*yv[rr]; ai[rr] += uin*yv[rr];
                ar[rr] += vhr*gv[rr]; az[rr] += vhz*gv[rr]; ah[rr] += vhn*gv[rr];
            }
        }
        #pragma unroll
        for (int rr=0; rr<8; rr++){
            float r = sig_f(ar[rr]);
            float z = sig_f(az[rr]);
            float nv = tanh_f(ai[rr] + r*ah[rr]);
            float hold = h1r[j*RPC + r0 + rr];
            h1w[j*RPC + r0 + rr] = nv + z*(hold - nv);
        }
        __syncthreads();
    }
    #pragma unroll
    for (int rr=0; rr<8; rr++){
        int n = nbase + rr;
        if (n < NN) g_hidden[n*HH + j] = sH1[j*RPC + r0 + rr];
    }
}

__global__ __launch_bounds__(512) void post_kernel(
    const float* __restrict__ trW, const float* __restrict__ trb, const float* __restrict__ a)
{
    __shared__ float sWt[HH*HH];
    __shared__ float sh[8*HH];
    __shared__ float sa[2*HH];
    __shared__ float sred[16][2];
    int tid = threadIdx.x;
    for (int idx=tid; idx<HH*HH; idx+=512){ int o=idx>>6, k=idx&63; sWt[k*HH+o]=trW[idx]; }
    if (tid < 2*HH) sa[tid] = a[tid];
    int lr = tid>>6, j = tid&63;
    int i = blockIdx.x*8 + lr;
    sh[lr*HH+j] = g_hidden[i*HH+j];
    __syncthreads();
    float acc = trb[j];
    #pragma unroll 8
    for (int k=0; k<HH; k++) acc += sWt[k*HH+j]*sh[lr*HH+k];
    float p1 = acc*sa[j], p2 = acc*sa[HH+j];
    #pragma unroll
    for (int off=16; off; off>>=1){
        p1 += __shfl_down_sync(0xffffffffu, p1, off);
        p2 += __shfl_down_sync(0xffffffffu, p2, off);
    }
    int wid = tid>>5;
    if ((tid&31)==0){ sred[wid][0]=p1; sred[wid][1]=p2; }
    __syncthreads();
    if (tid < 8){
        float s1 = sred[2*tid][0] + sred[2*tid+1][0];
        float s2 = sred[2*tid][1] + sred[2*tid+1][1];
        int n = blockIdx.x*8 + tid;
        g_s1[n] = s1; g_s2[n] = s2;
        unsigned u = __float_as_uint(s1);
        u = (u & 0x80000000u) ? ~u : (u | 0x80000000u);
        g_keys[n] = ((unsigned long long)u << 32) | (unsigned)n;
    }
}

__global__ __launch_bounds__(1024) void sort_kernel(){
    extern __shared__ unsigned long long sk[];
    int tid = threadIdx.x;
    for (int i=tid; i<NN; i+=1024) sk[i] = g_keys[i];
    __syncthreads();
    for (int k=2; k<=NN; k<<=1){
        for (int j=k>>1; j>0; j>>=1){
            for (int i=tid; i<NN; i+=1024){
                int ixj = i^j;
                if (ixj > i){
                    unsigned long long va = sk[i], vb = sk[ixj];
                    bool up = ((i & k) == 0);
                    if ((va > vb) == up){ sk[i]=vb; sk[ixj]=va; }
                }
            }
            __syncthreads();
        }
    }
    for (int r=tid; r<NN; r+=1024){
        unsigned long long key = sk[r];
        int idx = (int)(key & 0xffffffffu);
        g_perm[r] = idx;
        g_s1s[r]  = g_s1[idx];
    }
}

__global__ __launch_bounds__(1024) void scan_kernel(){
    __shared__ double ssum[1024];
    int c = blockIdx.x, tid = threadIdx.x;
    int nscans = (c == 128) ? 2 : 1;
    for (int s=0; s<nscans; s++){
        double local[8], ts = 0.0;
        #pragma unroll
        for (int e=0; e<8; e++){
            int r = tid*8 + e;
            double s1v = (double)g_s1s[r];
            double w;
            if (c < 64)       w = exp(s1v)      * (double)g_hidden[g_perm[r]*HH + c];
            else if (c < 128) w = exp(0.01*s1v) * (double)g_hidden[g_perm[r]*HH + (c-64)];
            else              w = (s == 0) ? exp(s1v) : exp(0.01*s1v);
            local[e] = w; ts += w;
        }
        ssum[tid] = ts; __syncthreads();
        for (int off=1; off<1024; off<<=1){
            double v = ssum[tid];
            if (tid >= off) v += ssum[tid-off];
            __syncthreads(); ssum[tid] = v; __syncthreads();
        }
        double run = tid ? ssum[tid-1] : 0.0;
        #pragma unroll
        for (int e=0; e<8; e++){
            int r = tid*8 + e;
            if (c < 64)       g_prefP[r*HH + c]     = run;
            else if (c < 128) g_prefQ[r*HH + (c-64)] = run;
            else              g_prefE[r*2 + s]       = run;
            run += local[e];
        }
        if (tid == 1023){
            double tot = ssum[1023];
            if (c < 64)       g_prefP[NN*HH + c]      = tot;
            else if (c < 128) g_prefQ[NN*HH + (c-64)] = tot;
            else              g_prefE[NN*2 + s]       = tot;
        }
        __syncthreads();
    }
}

__global__ __launch_bounds__(256) void final_kernel(
    const float* __restrict__ fcW, const float* __restrict__ fcb,
    const float* __restrict__ outW, const float* __restrict__ outb,
    float* __restrict__ out)
{
    __shared__ float sFcT[HH*HH];
    __shared__ float sOw[HH], sFb[HH];
    __shared__ float sH[8][HH];
    int tid = threadIdx.x;
    for (int idx=tid; idx<HH*HH; idx+=256){ int o=idx>>6, k=idx&63; sFcT[k*HH+o]=fcW[idx]; }
    if (tid < HH){ sOw[tid]=outW[tid]; sFb[tid]=fcb[tid]; }
    int w = tid>>5, lane = tid&31;
    int i = blockIdx.x*8 + w;
    float s2 = g_s2[i];
    float thr = -s2;
    int lo = 0, hi = NN;
    while (lo < hi){ int mid = (lo+hi)>>1; if (g_s1s[mid] < thr) lo = mid+1; else hi = mid; }
    int m = lo;
    double e2p = exp((double)s2), e2n = exp(0.01*(double)s2);
    double den = e2p*(g_prefE[NN*2+0] - g_prefE[m*2+0]) + e2n*g_prefE[m*2+1];
    __syncthreads();
    #pragma unroll
    for (int q=0; q<2; q++){
        int d = lane + q*32;
        double Pt = g_prefP[NN*HH + d];
        double num = e2p*(Pt - g_prefP[m*HH + d]) + e2n*g_prefQ[m*HH + d];
        sH[w][d] = (float)(num/den) + g_hidden[i*HH + d];
    }
    __syncwarp();
    float partial = 0.f;
    #pragma unroll
    for (int q=0; q<2; q++){
        int o = lane + q*32;
        float acc = sFb[o];
        #pragma unroll 8
        for (int k=0; k<HH; k++) acc += sFcT[k*HH+o]*sH[w][k];
        acc = (acc >= 0.f) ? acc : 0.01f*acc;
        partial += acc*sOw[o];
    }
    #pragma unroll
    for (int off=16; off; off>>=1) partial += __shfl_down_sync(0xffffffffu, partial, off);
    if (lane == 0) out[i] = partial + outb[0];
}

extern "C" void kernel_launch(void* const* d_in, const int* in_sizes, int n_in,
                              void* d_out, int out_size)
{
    const float* x    = (const float*)d_in[0];
    const float* Wih0 = (const float*)d_in[1];
    const float* Whh0 = (const float*)d_in[2];
    const float* bih0 = (const float*)d_in[3];
    const float* bhh0 = (const float*)d_in[4];
    const float* Wih1 = (const float*)d_in[5];
    const float* Whh1 = (const float*)d_in[6];
    const float* bih1 = (const float*)d_in[7];
    const float* bhh1 = (const float*)d_in[8];
    const float* trW  = (const float*)d_in[9];
    const float* trb  = (const float*)d_in[10];
    const float* a    = (const float*)d_in[11];
    const float* fcW  = (const float*)d_in[12];
    const float* fcb  = (const float*)d_in[13];
    const float* outW = (const float*)d_in[14];
    const float* outb = (const float*)d_in[15];

    cudaFuncSetAttribute(gru_kernel,  cudaFuncAttributeMaxDynamicSharedMemorySize, 212480);
    cudaFuncSetAttribute(sort_kernel, cudaFuncAttributeMaxDynamicSharedMemorySize, 65536);

    transpose_kernel<<<(TT*DD*NN + 255)/256, 256>>>(x);
    gru_kernel<<<147, GRU_NTH, 212480>>>(Wih0, Whh0, bih0, bhh0, Wih1, Whh1, bih1, bhh1);
    post_kernel<<<NN/8, 512>>>(trW, trb, a);
    sort_kernel<<<1, 1024, 65536>>>();
    scan_kernel<<<129, 1024>>>();
    final_kernel<<<NN/8, 256>>>(fcW, fcb, outW, outb, (float*)d_out);
}

// round 4
// speedup vs baseline: 1.0023x; 1.0023x over previous
#include <cuda_runtime.h>
#include <math.h>

#define NN 8192
#define TT 60
#define DD 6
#define HH 64
#define GG 192
#define RPC 56
#define GRU_NTH 448
#define HB (HH*RPC)

__device__ float g_xt[TT*DD*NN];
__device__ float g_hidden[NN*HH];
__device__ float g_s1[NN];
__device__ float g_s2[NN];
__device__ unsigned long long g_keys[NN];
__device__ float g_s1s[NN];
__device__ int   g_perm[NN];
__device__ double g_e1[NN];
__device__ double g_e01[NN];
__device__ double g_prefP[(NN+1)*HH];
__device__ double g_prefQ[(NN+1)*HH];
__device__ double g_prefE[(NN+1)*2];

typedef unsigned long long ull;

__device__ __forceinline__ float sig_f(float x){ return 1.f/(1.f+__expf(-x)); }
__device__ __forceinline__ float tanh_f(float x){ return 1.f-2.f/(__expf(2.f*x)+1.f); }
__device__ __forceinline__ ull pk2(float a, float b){
    ull r; asm("mov.b64 %0, {%1,%2};" : "=l"(r) : "f"(a), "f"(b)); return r;
}
__device__ __forceinline__ void fma2(ull &d, ull a, ull b){
    asm("fma.rn.f32x2 %0, %1, %2, %0;" : "+l"(d) : "l"(a), "l"(b));
}
__device__ __forceinline__ float2 up2(ull v){
    float2 f; asm("mov.b64 {%0,%1}, %2;" : "=f"(f.x), "=f"(f.y) : "l"(v)); return f;
}

// ---- tiled transpose x[n][d*60+t] -> g_xt[(t*6+d)][n] ----
__global__ __launch_bounds__(256) void transpose_kernel(const float* __restrict__ x){
    __shared__ float tile[32][33];
    int cb = blockIdx.x*32, nb = blockIdx.y*32;
    int tx = threadIdx.x, ty = threadIdx.y;
    #pragma unroll
    for (int yy=ty; yy<32; yy+=8){
        int n = nb+yy, c = cb+tx;
        tile[yy][tx] = (c < DD*TT) ? x[n*(DD*TT) + c] : 0.f;
    }
    __syncthreads();
    #pragma unroll
    for (int yy=ty; yy<32; yy+=8){
        int c = cb+yy, n = nb+tx;
        if (c < DD*TT){
            int orow = (c % TT)*DD + c/TT;
            g_xt[orow*NN + n] = tile[tx][yy];
        }
    }
}

__global__ __launch_bounds__(GRU_NTH,1) void gru_kernel(
    const float* __restrict__ Wih0, const float* __restrict__ Whh0,
    const float* __restrict__ bih0, const float* __restrict__ bhh0,
    const float* __restrict__ Wih1, const float* __restrict__ Whh1,
    const float* __restrict__ bih1, const float* __restrict__ bhh1)
{
    extern __shared__ float sm[];
    float* sWhh0 = sm;
    float* sWih1 = sm + 12288;
    float* sWhh1 = sm + 24576;
    float* sWih0 = sm + 36864;
    float* sB    = sm + 38016;
    float* sH0   = sm + 38784;
    float* sH1   = sm + 45952;
    const int tid = threadIdx.x;

    for (int idx = tid; idx < GG*HH; idx += GRU_NTH){
        int o = idx >> 6, k = idx & 63;
        sWhh0[k*GG+o] = Whh0[idx];
        sWih1[k*GG+o] = Wih1[idx];
        sWhh1[k*GG+o] = Whh1[idx];
    }
    for (int idx = tid; idx < GG*DD; idx += GRU_NTH){
        int o = idx/DD, d = idx - o*DD;
        sWih0[d*GG+o] = Wih0[idx];
    }
    for (int idx = tid; idx < GG; idx += GRU_NTH){
        sB[idx]     = bih0[idx];
        sB[192+idx] = bhh0[idx];
        sB[384+idx] = bih1[idx];
        sB[576+idx] = bhh1[idx];
    }
    for (int idx = tid; idx < 2*HB; idx += GRU_NTH){ sH0[idx]=0.f; sH1[idx]=0.f; }
    __syncthreads();

    const int j  = tid & 63;
    const int r0 = (tid >> 6) << 3;
    const int nbase = blockIdx.x*RPC + r0;
    const bool v8 = (nbase + 7) < NN;

    const ull b0r2 = pk2(sB[j]      + sB[192+j], sB[j]      + sB[192+j]);
    const ull b0z2 = pk2(sB[64+j]   + sB[256+j], sB[64+j]   + sB[256+j]);
    const ull b0i2 = pk2(sB[128+j], sB[128+j]);
    const ull b0h2 = pk2(sB[320+j], sB[320+j]);
    const ull b1r2 = pk2(sB[384+j]  + sB[576+j], sB[384+j]  + sB[576+j]);
    const ull b1z2 = pk2(sB[448+j]  + sB[640+j], sB[448+j]  + sB[640+j]);
    const ull b1i2 = pk2(sB[512+j], sB[512+j]);
    const ull b1h2 = pk2(sB[704+j], sB[704+j]);

    #pragma unroll 1
    for (int t = 0; t < TT; t++){
        const int p = t & 1;
        const float* h0r = sH0 + p*HB;
        float*       h0w = sH0 + (p^1)*HB;
        ull ar[4], az[4], ai[4], ah[4];
        #pragma unroll
        for (int q=0;q<4;q++){ ar[q]=b0r2; az[q]=b0z2; ai[q]=b0i2; ah[q]=b0h2; }

        #pragma unroll
        for (int d=0; d<DD; d++){
            ull xv2[4];
            const float* xp = g_xt + (t*DD+d)*NN + nbase;
            if (v8){
                ulonglong2 a = *(const ulonglong2*)xp;
                ulonglong2 b = *(const ulonglong2*)(xp+4);
                xv2[0]=a.x; xv2[1]=a.y; xv2[2]=b.x; xv2[3]=b.y;
            } else {
                float xs[8];
                #pragma unroll
                for (int rr=0; rr<8; rr++) xs[rr] = (nbase+rr < NN) ? xp[rr] : 0.f;
                #pragma unroll
                for (int q=0;q<4;q++) xv2[q] = pk2(xs[2*q], xs[2*q+1]);
            }
            float wr = sWih0[d*GG+j], wz = sWih0[d*GG+64+j], wn = sWih0[d*GG+128+j];
            ull wr2 = pk2(wr,wr), wz2 = pk2(wz,wz), wn2 = pk2(wn,wn);
            #pragma unroll
            for (int q=0;q<4;q++){
                fma2(ar[q], wr2, xv2[q]); fma2(az[q], wz2, xv2[q]); fma2(ai[q], wn2, xv2[q]);
            }
        }
        #pragma unroll 8
        for (int k=0; k<HH; k++){
            float wr = sWhh0[k*GG+j], wz = sWhh0[k*GG+64+j], wn = sWhh0[k*GG+128+j];
            ull wr2 = pk2(wr,wr), wz2 = pk2(wz,wz), wn2 = pk2(wn,wn);
            ulonglong2 ha = *(const ulonglong2*)(h0r + k*RPC + r0);
            ulonglong2 hb = *(const ulonglong2*)(h0r + k*RPC + r0 + 4);
            ull hv2[4] = {ha.x, ha.y, hb.x, hb.y};
            #pragma unroll
            for (int q=0;q<4;q++){
                fma2(ar[q], wr2, hv2[q]); fma2(az[q], wz2, hv2[q]); fma2(ah[q], wn2, hv2[q]);
            }
        }
        #pragma unroll
        for (int q=0;q<4;q++){
            float2 fr = up2(ar[q]), fz = up2(az[q]), fi = up2(ai[q]), fh = up2(ah[q]);
            {
                float r = sig_f(fr.x), z = sig_f(fz.x);
                float nv = tanh_f(fi.x + r*fh.x);
                float hold = h0r[j*RPC + r0 + 2*q];
                h0w[j*RPC + r0 + 2*q] = nv + z*(hold - nv);
            }
            {
                float r = sig_f(fr.y), z = sig_f(fz.y);
                float nv = tanh_f(fi.y + r*fh.y);
                float hold = h0r[j*RPC + r0 + 2*q+1];
                h0w[j*RPC + r0 + 2*q+1] = nv + z*(hold - nv);
            }
        }
        __syncthreads();

        const float* h1r = sH1 + p*HB;
        float*       h1w = sH1 + (p^1)*HB;
        #pragma unroll
        for (int q=0;q<4;q++){ ar[q]=b1r2; az[q]=b1z2; ai[q]=b1i2; ah[q]=b1h2; }
        #pragma unroll 4
        for (int k=0; k<HH; k++){
            float uir = sWih1[k*GG+j], uiz = sWih1[k*GG+64+j], uin = sWih1[k*GG+128+j];
            float vhr = sWhh1[k*GG+j], vhz = sWhh1[k*GG+64+j], vhn = sWhh1[k*GG+128+j];
            ull uir2 = pk2(uir,uir), uiz2 = pk2(uiz,uiz), uin2 = pk2(uin,uin);
            ull vhr2 = pk2(vhr,vhr), vhz2 = pk2(vhz,vhz), vhn2 = pk2(vhn,vhn);
            ulonglong2 ya = *(const ulonglong2*)(h0w + k*RPC + r0);
            ulonglong2 yb = *(const ulonglong2*)(h0w + k*RPC + r0 + 4);
            ulonglong2 ga = *(const ulonglong2*)(h1r + k*RPC + r0);
            ulonglong2 gb = *(const ulonglong2*)(h1r + k*RPC + r0 + 4);
            ull yv2[4] = {ya.x, ya.y, yb.x, yb.y};
            ull gv2[4] = {ga.x, ga.y, gb.x, gb.y};
            #pragma unroll
            for (int q=0;q<4;q++){
                fma2(ar[q], uir2, yv2[q]); fma2(az[q], uiz2, yv2[q]); fma2(ai[q], uin2, yv2[q]);
                fma2(ar[q], vhr2, gv2[q]); fma2(az[q], vhz2, gv2[q]); fma2(ah[q], vhn2, gv2[q]);
            }
        }
        #pragma unroll
        for (int q=0;q<4;q++){
            float2 fr = up2(ar[q]), fz = up2(az[q]), fi = up2(ai[q]), fh = up2(ah[q]);
            {
                float r = sig_f(fr.x), z = sig_f(fz.x);
                float nv = tanh_f(fi.x + r*fh.x);
                float hold = h1r[j*RPC + r0 + 2*q];
                h1w[j*RPC + r0 + 2*q] = nv + z*(hold - nv);
            }
            {
                float r = sig_f(fr.y), z = sig_f(fz.y);
                float nv = tanh_f(fi.y + r*fh.y);
                float hold = h1r[j*RPC + r0 + 2*q+1];
                h1w[j*RPC + r0 + 2*q+1] = nv + z*(hold - nv);
            }
        }
        __syncthreads();
    }
    #pragma unroll
    for (int rr=0; rr<8; rr++){
        int n = nbase + rr;
        if (n < NN) g_hidden[n*HH + j] = sH1[j*RPC + r0 + rr];
    }
}

__global__ __launch_bounds__(512) void post_kernel(
    const float* __restrict__ trW, const float* __restrict__ trb, const float* __restrict__ a)
{
    __shared__ float sWt[HH*HH];
    __shared__ float sh[8*HH];
    __shared__ float sa[2*HH];
    __shared__ float sred[16][2];
    int tid = threadIdx.x;
    for (int idx=tid; idx<HH*HH; idx+=512){ int o=idx>>6, k=idx&63; sWt[k*HH+o]=trW[idx]; }
    if (tid < 2*HH) sa[tid] = a[tid];
    int lr = tid>>6, j = tid&63;
    int i = blockIdx.x*8 + lr;
    sh[lr*HH+j] = g_hidden[i*HH+j];
    __syncthreads();
    float acc = trb[j];
    #pragma unroll 8
    for (int k=0; k<HH; k++) acc += sWt[k*HH+j]*sh[lr*HH+k];
    float p1 = acc*sa[j], p2 = acc*sa[HH+j];
    #pragma unroll
    for (int off=16; off; off>>=1){
        p1 += __shfl_down_sync(0xffffffffu, p1, off);
        p2 += __shfl_down_sync(0xffffffffu, p2, off);
    }
    int wid = tid>>5;
    if ((tid&31)==0){ sred[wid][0]=p1; sred[wid][1]=p2; }
    __syncthreads();
    if (tid < 8){
        float s1 = sred[2*tid][0] + sred[2*tid+1][0];
        float s2 = sred[2*tid][1] + sred[2*tid+1][1];
        int n = blockIdx.x*8 + tid;
        g_s1[n] = s1; g_s2[n] = s2;
        unsigned u = __float_as_uint(s1);
        u = (u & 0x80000000u) ? ~u : (u | 0x80000000u);
        g_keys[n] = ((unsigned long long)u << 32) | (unsigned)n;
    }
}

__global__ __launch_bounds__(1024) void sort_kernel(){
    extern __shared__ unsigned long long sk[];
    int tid = threadIdx.x;
    for (int i=tid; i<NN; i+=1024) sk[i] = g_keys[i];
    __syncthreads();
    for (int k=2; k<=NN; k<<=1){
        // smem phases for j >= 8
        for (int j=k>>1; j>=8; j>>=1){
            for (int i=tid; i<NN; i+=1024){
                int ixj = i^j;
                if (ixj > i){
                    unsigned long long va = sk[i], vb = sk[ixj];
                    bool up = ((i & k) == 0);
                    if ((va > vb) == up){ sk[i]=vb; sk[ixj]=va; }
                }
            }
            __syncthreads();
        }
        // register phases: j in {4,2,1} within each thread's aligned 8-chunk
        {
            int base = tid*8;
            unsigned long long v[8];
            #pragma unroll
            for (int e=0;e<8;e++) v[e] = sk[base+e];
            #pragma unroll
            for (int jj=4; jj>=1; jj>>=1){
                if (jj <= (k>>1)){
                    #pragma unroll
                    for (int e=0;e<8;e++){
                        int i = base+e, ixj = i^jj;
                        if (ixj > i){
                            bool up = ((i & k) == 0);
                            unsigned long long va=v[e], vb=v[ixj-base];
                            if ((va > vb) == up){ v[e]=vb; v[ixj-base]=va; }
                        }
                    }
                }
            }
            #pragma unroll
            for (int e=0;e<8;e++) sk[base+e] = v[e];
            __syncthreads();
        }
    }
    for (int r=tid; r<NN; r+=1024){
        unsigned long long key = sk[r];
        int idx = (int)(key & 0xffffffffu);
        g_perm[r] = idx;
        float s1v = g_s1[idx];
        g_s1s[r]  = s1v;
        g_e1[r]  = exp((double)s1v);
        g_e01[r] = exp(0.01*(double)s1v);
    }
}

__global__ __launch_bounds__(1024) void scan_kernel(){
    __shared__ double ssum[1024];
    int c = blockIdx.x, tid = threadIdx.x;
    int nscans = (c == 128) ? 2 : 1;
    for (int s=0; s<nscans; s++){
        double local[8], ts = 0.0;
        #pragma unroll
        for (int e=0; e<8; e++){
            int r = tid*8 + e;
            double w;
            if (c < 64)       w = g_e1[r]  * (double)g_hidden[g_perm[r]*HH + c];
            else if (c < 128) w = g_e01[r] * (double)g_hidden[g_perm[r]*HH + (c-64)];
            else              w = (s == 0) ? g_e1[r] : g_e01[r];
            local[e] = w; ts += w;
        }
        ssum[tid] = ts; __syncthreads();
        for (int off=1; off<1024; off<<=1){
            double v = ssum[tid];
            if (tid >= off) v += ssum[tid-off];
            __syncthreads(); ssum[tid] = v; __syncthreads();
        }
        double run = tid ? ssum[tid-1] : 0.0;
        #pragma unroll
        for (int e=0; e<8; e++){
            int r = tid*8 + e;
            if (c < 64)       g_prefP[r*HH + c]      = run;
            else if (c < 128) g_prefQ[r*HH + (c-64)] = run;
            else              g_prefE[r*2 + s]        = run;
            run += local[e];
        }
        if (tid == 1023){
            double tot = ssum[1023];
            if (c < 64)       g_prefP[NN*HH + c]      = tot;
            else if (c < 128) g_prefQ[NN*HH + (c-64)] = tot;
            else              g_prefE[NN*2 + s]        = tot;
        }
        __syncthreads();
    }
}

__global__ __launch_bounds__(256) void final_kernel(
    const float* __restrict__ fcW, const float* __restrict__ fcb,
    const float* __restrict__ outW, const float* __restrict__ outb,
    float* __restrict__ out)
{
    __shared__ float sFcT[HH*HH];
    __shared__ float sOw[HH], sFb[HH];
    __shared__ float sH[8][HH];
    int tid = threadIdx.x;
    for (int idx=tid; idx<HH*HH; idx+=256){ int o=idx>>6, k=idx&63; sFcT[k*HH+o]=fcW[idx]; }
    if (tid < HH){ sOw[tid]=outW[tid]; sFb[tid]=fcb[tid]; }
    int w = tid>>5, lane = tid&31;
    int i = blockIdx.x*8 + w;
    float s2 = g_s2[i];
    float thr = -s2;
    int lo = 0, hi = NN;
    while (lo < hi){ int mid = (lo+hi)>>1; if (g_s1s[mid] < thr) lo = mid+1; else hi = mid; }
    int m = lo;
    double e2p = exp((double)s2), e2n = exp(0.01*(double)s2);
    double den = e2p*(g_prefE[NN*2+0] - g_prefE[m*2+0]) + e2n*g_prefE[m*2+1];
    __syncthreads();
    #pragma unroll
    for (int q=0; q<2; q++){
        int d = lane + q*32;
        double Pt = g_prefP[NN*HH + d];
        double num = e2p*(Pt - g_prefP[m*HH + d]) + e2n*g_prefQ[m*HH + d];
        sH[w][d] = (float)(num/den) + g_hidden[i*HH + d];
    }
    __syncwarp();
    float partial = 0.f;
    #pragma unroll
    for (int q=0; q<2; q++){
        int o = lane + q*32;
        float acc = sFb[o];
        #pragma unroll 8
        for (int k=0; k<HH; k++) acc += sFcT[k*HH+o]*sH[w][k];
        acc = (acc >= 0.f) ? acc : 0.01f*acc;
        partial += acc*sOw[o];
    }
    #pragma unroll
    for (int off=16; off; off>>=1) partial += __shfl_down_sync(0xffffffffu, partial, off);
    if (lane == 0) out[i] = partial + outb[0];
}

extern "C" void kernel_launch(void* const* d_in, const int* in_sizes, int n_in,
                              void* d_out, int out_size)
{
    const float* x    = (const float*)d_in[0];
    const float* Wih0 = (const float*)d_in[1];
    const float* Whh0 = (const float*)d_in[2];
    const float* bih0 = (const float*)d_in[3];
    const float* bhh0 = (const float*)d_in[4];
    const float* Wih1 = (const float*)d_in[5];
    const float* Whh1 = (const float*)d_in[6];
    const float* bih1 = (const float*)d_in[7];
    const float* bhh1 = (const float*)d_in[8];
    const float* trW  = (const float*)d_in[9];
    const float* trb  = (const float*)d_in[10];
    const float* a    = (const float*)d_in[11];
    const float* fcW  = (const float*)d_in[12];
    const float* fcb  = (const float*)d_in[13];
    const float* outW = (const float*)d_in[14];
    const float* outb = (const float*)d_in[15];

    cudaFuncSetAttribute(gru_kernel,  cudaFuncAttributeMaxDynamicSharedMemorySize, 212480);
    cudaFuncSetAttribute(sort_kernel, cudaFuncAttributeMaxDynamicSharedMemorySize, 65536);

    dim3 tb(32, 8);
    dim3 tg((DD*TT + 31)/32, NN/32);
    transpose_kernel<<<tg, tb>>>(x);
    gru_kernel<<<147, GRU_NTH, 212480>>>(Wih0, Whh0, bih0, bhh0, Wih1, Whh1, bih1, bhh1);
    post_kernel<<<NN/8, 512>>>(trW, trb, a);
    sort_kernel<<<1, 1024, 65536>>>();
    scan_kernel<<<129, 1024>>>();
    final_kernel<<<NN/8, 256>>>(fcW, fcb, outW, outb, (float*)d_out);
}